// round 14
// baseline (speedup 1.0000x reference)
#include <cuda_runtime.h>
#include <cuda_bf16.h>
#include <math.h>

// ---------------- constants ----------------
#define BATCH   32
#define HDIM    2048
#define NHEADS  16
#define HEADD   128
#define DFF     8192
#define QKV_N   (3*HDIM)   // 6144
#define MAXS    2048
#define MAXBLK  32
#define PAGE    64
#define NUMBLK  1024
#define NSPLIT  32
#define CHUNK   64         // MAXS / NSPLIT == one KV page
#define TKC     32         // gemm k-chunk
#define TN      128        // gemm n-tile
#define NSTAGE  3          // gemm pipeline stages

// ---------------- scratch (no allocs allowed) ----------------
__device__ float g_x1 [BATCH*HDIM];
__device__ float g_q  [BATCH*HDIM];      // only Q is needed (ref discards K,V cols)
__device__ float g_att[BATCH*HDIM];
__device__ float g_h  [BATCH*HDIM];
__device__ float g_x2 [BATCH*HDIM];
__device__ float g_ffn[BATCH*DFF];
__device__ float g_pm [BATCH*NHEADS*NSPLIT];
__device__ float g_ps [BATCH*NHEADS*NSPLIT];
__device__ float g_pa [BATCH*NHEADS*NSPLIT*HEADD];

// ---------------- helpers ----------------
__device__ __forceinline__ float gelu_exact(float x) {
    return 0.5f * x * (1.0f + erff(x * 0.70710678118654752f));
}

// unbiased rounding to tf32 (A and W — biased truncation measured 2x worse err)
__device__ __forceinline__ unsigned rna_tf32(float x) {
    unsigned h;
    asm("cvt.rna.tf32.f32 %0, %1;" : "=r"(h) : "f"(x));
    return h;
}

__device__ __forceinline__ void mma_tf32(float d[4], const unsigned a[4],
                                         unsigned b0, unsigned b1) {
    asm volatile(
        "mma.sync.aligned.m16n8k8.row.col.f32.tf32.tf32.f32 "
        "{%0,%1,%2,%3}, {%4,%5,%6,%7}, {%8,%9}, {%0,%1,%2,%3};"
        : "+f"(d[0]), "+f"(d[1]), "+f"(d[2]), "+f"(d[3])
        : "r"(a[0]), "r"(a[1]), "r"(a[2]), "r"(a[3]), "r"(b0), "r"(b1));
}

__device__ __forceinline__ void cp_async16(void* smem, const void* g) {
    unsigned s = (unsigned)__cvta_generic_to_shared(smem);
    asm volatile("cp.async.cg.shared.global [%0], [%1], 16;" :: "r"(s), "l"(g));
}
__device__ __forceinline__ void cp_commit() {
    asm volatile("cp.async.commit_group;");
}
template<int N>
__device__ __forceinline__ void cp_wait() {
    asm volatile("cp.async.wait_group %0;" :: "n"(N));
}

// ---------------- LN body (one block, one row) ----------------
__device__ __forceinline__ void ln_row(
    const float* __restrict__ xr, const float* __restrict__ g,
    const float* __restrict__ b, float* __restrict__ yr)
{
    float s = 0.f, s2 = 0.f;
    for (int i = threadIdx.x; i < HDIM; i += 256) {
        float v = xr[i]; s += v; s2 += v * v;
    }
    __shared__ float sh[16];
    int lane = threadIdx.x & 31, w = threadIdx.x >> 5;
    #pragma unroll
    for (int o = 16; o; o >>= 1) {
        s  += __shfl_xor_sync(0xffffffffu, s,  o);
        s2 += __shfl_xor_sync(0xffffffffu, s2, o);
    }
    if (lane == 0) { sh[w] = s; sh[8 + w] = s2; }
    __syncthreads();
    if (threadIdx.x == 0) {
        float S = 0.f, S2 = 0.f;
        #pragma unroll
        for (int i = 0; i < 8; i++) { S += sh[i]; S2 += sh[8 + i]; }
        sh[0] = S; sh[1] = S2;
    }
    __syncthreads();
    float mu  = sh[0] * (1.0f / HDIM);
    float var = sh[1] * (1.0f / HDIM) - mu * mu;
    float inv = rsqrtf(var + 1e-5f);
    for (int i = threadIdx.x; i < HDIM; i += 256)
        yr[i] = (xr[i] - mu) * inv * g[i] + b[i];
}

// ---------------- phase 1: ln1 rows + init q/h/ffn (independent outputs) -----
__global__ void __launch_bounds__(256) ln1_init_kernel(
    const float* __restrict__ hidden,
    const float* __restrict__ ln1g, const float* __restrict__ ln1b,
    float* __restrict__ x1,
    float* __restrict__ q, const float* __restrict__ battn,
    float* __restrict__ h, const float* __restrict__ bproj,
    float* __restrict__ ffn, const float* __restrict__ bfc)
{
    if (blockIdx.x < BATCH) {
        int row = blockIdx.x;
        ln_row(hidden + row * HDIM, ln1g, ln1b, x1 + row * HDIM);
        return;
    }
    const int gix = blockIdx.x - BATCH;
    const int gnum = gridDim.x - BATCH;
    const int n1 = BATCH * HDIM;              // q
    const int n2 = n1 + BATCH * HDIM;         // h
    const int n3 = n2 + BATCH * DFF;          // ffn
    for (int i = gix * 256 + threadIdx.x; i < n3; i += gnum * 256) {
        if (i < n1) {
            q[i] = battn[i & (HDIM - 1)];
        } else if (i < n2) {
            int j = i - n1;
            h[j] = bproj[j & (HDIM - 1)] + hidden[j];
        } else {
            int j = i - n2;
            ffn[j] = bfc[j & (DFF - 1)];
        }
    }
}

// ---------------- phase 2: ln2 rows + out = h + b_fc2 (both depend on h) ----
__global__ void __launch_bounds__(256) ln2_init_kernel(
    const float* __restrict__ h,
    const float* __restrict__ ln2g, const float* __restrict__ ln2b,
    float* __restrict__ x2,
    float* __restrict__ out, const float* __restrict__ bfc2)
{
    if (blockIdx.x < BATCH) {
        int row = blockIdx.x;
        ln_row(h + row * HDIM, ln2g, ln2b, x2 + row * HDIM);
        return;
    }
    const int gix = blockIdx.x - BATCH;
    const int gnum = gridDim.x - BATCH;
    const int n = BATCH * HDIM;
    for (int i = gix * 256 + threadIdx.x; i < n; i += gnum * 256) {
        out[i] = h[i] + bfc2[i & (HDIM - 1)];
    }
}

// ---------------- elementwise gelu (in place, float4) ----------------
__global__ void __launch_bounds__(256) gelu_kernel(float* __restrict__ x, int n4)
{
    int i = blockIdx.x * 256 + threadIdx.x;
    if (i < n4) {
        float4 v = reinterpret_cast<float4*>(x)[i];
        v.x = gelu_exact(v.x); v.y = gelu_exact(v.y);
        v.z = gelu_exact(v.z); v.w = gelu_exact(v.w);
        reinterpret_cast<float4*>(x)[i] = v;
    }
}

// ---------------- tensor-core GEMM: C[32,Nout] += A[32,K] @ W[K,:Nout] -------
// 1xTF32, A and W rna-rounded (unbiased). 3-stage cp.async ring, 3 CTAs/SM,
// one barrier per chunk. ldW = W row stride (allows slicing w_attn to Q cols).
// Wave-balanced uneven split-K. atomicAdd into bias-preinitialized C.
#define WS_FL (TKC*136)
#define AS_FL (32*36)
#define GEMM_SMEM (NSTAGE*(WS_FL+AS_FL)*4)
__global__ void __launch_bounds__(256, 3) gemm_tc(
    const float* __restrict__ A, const float* __restrict__ W,
    float* __restrict__ C, int K, int Nout, int ldW)
{
    extern __shared__ float smp[];
    float (*Ws)[TKC][136] = reinterpret_cast<float(*)[TKC][136]>(smp);
    float (*As)[32][36]   = reinterpret_cast<float(*)[32][36]>(smp + NSTAGE * WS_FL);

    int tid = threadIdx.x;
    int lane = tid & 31, warp = tid >> 5;
    int m0 = (warp & 1) * 16;
    int n0w = (warp >> 1) * 32;
    int nblk = blockIdx.x * TN;

    int cchunks = K / TKC;
    int c0 = (int)(((long long)cchunks * blockIdx.y)       / gridDim.y);
    int c1 = (int)(((long long)cchunks * (blockIdx.y + 1)) / gridDim.y);
    int kbeg = c0 * TKC;
    int nchunk = c1 - c0;

    float acc[4][4] = {};

    int am = tid >> 3, ak = (tid & 7) * 4;   // A staging coords (1 seg/thread)
    int gr = lane >> 2, kq = lane & 3;       // fragment coords

    auto prefetch = [&](int chunk) {
        int kb = kbeg + chunk * TKC;
        int s = chunk % NSTAGE;
        cp_async16(&As[s][am][ak], &A[am * K + kb + ak]);
        #pragma unroll
        for (int it = 0; it < 4; ++it) {
            int idx = it * 256 + tid;
            int kk = idx >> 5, c4 = (idx & 31) * 4;
            cp_async16(&Ws[s][kk][c4], &W[(size_t)(kb + kk) * ldW + nblk + c4]);
        }
    };

    #pragma unroll
    for (int c = 0; c < NSTAGE - 1; ++c) {
        if (c < nchunk) prefetch(c);
        cp_commit();
    }

    for (int i = 0; i < nchunk; ++i) {
        cp_wait<NSTAGE - 2>();    // group i complete
        __syncthreads();          // all warps done with compute(i-1) and see stage i
        if (i + NSTAGE - 1 < nchunk) prefetch(i + NSTAGE - 1);
        cp_commit();
        int s = i % NSTAGE;
        #pragma unroll
        for (int ks = 0; ks < 4; ++ks) {
            int k0 = ks * 8;
            unsigned ah[4];
            ah[0] = rna_tf32(As[s][m0 + gr    ][k0 + kq    ]);
            ah[1] = rna_tf32(As[s][m0 + gr + 8][k0 + kq    ]);
            ah[2] = rna_tf32(As[s][m0 + gr    ][k0 + kq + 4]);
            ah[3] = rna_tf32(As[s][m0 + gr + 8][k0 + kq + 4]);
            #pragma unroll
            for (int nt = 0; nt < 4; ++nt) {
                int nb2 = n0w + nt * 8 + gr;
                unsigned bh0 = rna_tf32(Ws[s][k0 + kq    ][nb2]);
                unsigned bh1 = rna_tf32(Ws[s][k0 + kq + 4][nb2]);
                mma_tf32(acc[nt], ah, bh0, bh1);
            }
        }
    }

    int cq = (lane & 3) * 2;
    #pragma unroll
    for (int nt = 0; nt < 4; ++nt) {
        int col = nblk + n0w + nt * 8 + cq;
        atomicAdd(&C[(m0 + gr    ) * Nout + col    ], acc[nt][0]);
        atomicAdd(&C[(m0 + gr    ) * Nout + col + 1], acc[nt][1]);
        atomicAdd(&C[(m0 + gr + 8) * Nout + col    ], acc[nt][2]);
        atomicAdd(&C[(m0 + gr + 8) * Nout + col + 1], acc[nt][3]);
    }
}

// ---------------- attention partial: one block per (b,h,page) ----------------
__global__ void __launch_bounds__(256) attn_partial(
    const float* __restrict__ q, const float* __restrict__ kv,
    const int* __restrict__ bt, const int* __restrict__ sl,
    float* __restrict__ pm, float* __restrict__ ps, float* __restrict__ pa)
{
    int b = blockIdx.x, h = blockIdx.y, sp = blockIdx.z;
    int tid = threadIdx.x, lane = tid & 31, w = tid >> 5;
    int pidx = (b * NHEADS + h) * NSPLIT + sp;
    int seq = sl[b];
    int t0 = sp * CHUNK;
    if (t0 >= seq) {
        if (tid == 0) { pm[pidx] = -INFINITY; ps[pidx] = 0.f; }
        return;
    }
    int nt = seq - t0; if (nt > CHUNK) nt = CHUNK;

    __shared__ float qs[HEADD];
    __shared__ float sc[CHUNK];
    __shared__ int   rbs;              // page base (float index, < 2^31)
    __shared__ float sa[2][HEADD];

    if (tid < HEADD) qs[tid] = q[b * HDIM + h * HEADD + tid];
    if (tid == 0)
        rbs = bt[b * MAXBLK + sp] * (PAGE * NHEADS * HEADD) + h * HEADD;
    __syncthreads();
    int rb = rbs;

    const float scale = 0.08838834764831845f;  // 1/sqrt(128)
    float4 qx = reinterpret_cast<const float4*>(qs)[lane];

    // pass 1: scores. 4 tokens/warp/iter (loads clamped to page row 63 — always
    // resident; stores guarded by nt). Interleaved shfl chains pipeline.
    for (int tb = w * 4; tb < nt; tb += 32) {
        int u1 = min(tb + 1, 63), u2 = min(tb + 2, 63), u3 = min(tb + 3, 63);
        const float* base = kv + rb;
        float4 ka = reinterpret_cast<const float4*>(base + tb * (NHEADS * HEADD))[lane];
        float4 kb2 = reinterpret_cast<const float4*>(base + u1 * (NHEADS * HEADD))[lane];
        float4 kc2 = reinterpret_cast<const float4*>(base + u2 * (NHEADS * HEADD))[lane];
        float4 kd2 = reinterpret_cast<const float4*>(base + u3 * (NHEADS * HEADD))[lane];
        float d0 = ka.x  * qx.x + ka.y  * qx.y + ka.z  * qx.z + ka.w  * qx.w;
        float d1 = kb2.x * qx.x + kb2.y * qx.y + kb2.z * qx.z + kb2.w * qx.w;
        float d2 = kc2.x * qx.x + kc2.y * qx.y + kc2.z * qx.z + kc2.w * qx.w;
        float d3 = kd2.x * qx.x + kd2.y * qx.y + kd2.z * qx.z + kd2.w * qx.w;
        #pragma unroll
        for (int o = 16; o; o >>= 1) {
            d0 += __shfl_xor_sync(0xffffffffu, d0, o);
            d1 += __shfl_xor_sync(0xffffffffu, d1, o);
            d2 += __shfl_xor_sync(0xffffffffu, d2, o);
            d3 += __shfl_xor_sync(0xffffffffu, d3, o);
        }
        if (lane == 0) {
            sc[tb] = d0 * scale;
            if (tb + 1 < nt) sc[tb + 1] = d1 * scale;
            if (tb + 2 < nt) sc[tb + 2] = d2 * scale;
            if (tb + 3 < nt) sc[tb + 3] = d3 * scale;
        }
    }
    __syncthreads();

    // softmax stats in ONE warp (nt <= 64 -> 2 values/lane), then one barrier.
    if (w == 0) {
        float v0 = (lane      < nt) ? sc[lane]      : -INFINITY;
        float v1 = (lane + 32 < nt) ? sc[lane + 32] : -INFINITY;
        float m = fmaxf(v0, v1);
        #pragma unroll
        for (int o = 16; o; o >>= 1) m = fmaxf(m, __shfl_xor_sync(0xffffffffu, m, o));
        float e0 = (lane      < nt) ? __expf(v0 - m) : 0.f;
        float e1 = (lane + 32 < nt) ? __expf(v1 - m) : 0.f;
        if (lane      < nt) sc[lane]      = e0;
        if (lane + 32 < nt) sc[lane + 32] = e1;
        float s = e0 + e1;
        #pragma unroll
        for (int o = 16; o; o >>= 1) s += __shfl_xor_sync(0xffffffffu, s, o);
        if (lane == 0) { pm[pidx] = m; ps[pidx] = s; }
    }
    __syncthreads();

    // pass 2: unnormalized weighted V. 2 halves x 4-way unroll.
    int d = tid & 127, half = tid >> 7;
    const float* Vb = kv + (size_t)NUMBLK * PAGE * NHEADS * HEADD;
    float a0 = 0.f, a1 = 0.f, a2 = 0.f, a3 = 0.f;
    int t = half;
    for (; t + 6 < nt; t += 8) {
        const float* v0 = Vb + rb + (t    ) * (NHEADS * HEADD);
        const float* v1 = Vb + rb + (t + 2) * (NHEADS * HEADD);
        const float* v2 = Vb + rb + (t + 4) * (NHEADS * HEADD);
        const float* v3 = Vb + rb + (t + 6) * (NHEADS * HEADD);
        a0 += sc[t    ] * v0[d];
        a1 += sc[t + 2] * v1[d];
        a2 += sc[t + 4] * v2[d];
        a3 += sc[t + 6] * v3[d];
    }
    for (; t < nt; t += 2) {
        const float* vr = Vb + rb + t * (NHEADS * HEADD);
        a0 += sc[t] * vr[d];
    }
    sa[half][d] = (a0 + a1) + (a2 + a3);
    __syncthreads();
    if (tid < HEADD) pa[(size_t)pidx * HEADD + tid] = sa[0][tid] + sa[1][tid];
}

// ---------------- attention combine: one block per (b,h), 512 threads -------
// 4 split-groups of 8: each thread loads 8 pa values (independent), partial
// sums reduced through smem. den/M recomputed per-thread from smem stats.
__global__ void __launch_bounds__(512) attn_combine(
    const float* __restrict__ pm, const float* __restrict__ ps,
    const float* __restrict__ pa, float* __restrict__ out)
{
    int b = blockIdx.x, h = blockIdx.y;
    int idx = b * NHEADS + h;
    int tid = threadIdx.x;
    int d = tid & 127, g = tid >> 7;          // g in 0..3, 8 splits each
    __shared__ float ms[NSPLIT], ss[NSPLIT];
    __shared__ float part[4][HEADD];
    if (tid < NSPLIT) {
        ms[tid] = pm[idx * NSPLIT + tid];
        ss[tid] = ps[idx * NSPLIT + tid];
    }
    __syncthreads();

    // global max + denominator (scalar, redundant per thread — cheap)
    float M = -INFINITY;
    #pragma unroll
    for (int i = 0; i < NSPLIT; i++)
        if (ss[i] > 0.f) M = fmaxf(M, ms[i]);
    float den = 0.f;
    #pragma unroll
    for (int i = 0; i < NSPLIT; i++)
        if (ss[i] > 0.f) den += __expf(ms[i] - M) * ss[i];

    // numerator: this group's 8 splits (independent global loads)
    const float* pab = pa + (size_t)idx * NSPLIT * HEADD;
    float num = 0.f;
    #pragma unroll
    for (int k = 0; k < 8; k++) {
        int i = g * 8 + k;
        if (ss[i] > 0.f)
            num += __expf(ms[i] - M) * pab[i * HEADD + d];
    }
    part[g][d] = num;
    __syncthreads();
    if (g == 0)
        out[b * HDIM + h * HEADD + d] =
            (part[0][d] + part[1][d] + part[2][d] + part[3][d]) / den;
}

// ---------------- host launcher ----------------
extern "C" void kernel_launch(void* const* d_in, const int* in_sizes, int n_in,
                              void* d_out, int out_size)
{
    const float* hidden = (const float*)d_in[0];
    const float* kv     = (const float*)d_in[1];
    const int*   bt     = (const int*)d_in[2];
    const int*   sl     = (const int*)d_in[3];
    int p = (n_in > 4 && in_sizes[4] == 1) ? 5 : 4;  // skip max_seq_len if present
    const float* ln1g  = (const float*)d_in[p + 0];
    const float* ln1b  = (const float*)d_in[p + 1];
    const float* ln2g  = (const float*)d_in[p + 2];
    const float* ln2b  = (const float*)d_in[p + 3];
    const float* wattn = (const float*)d_in[p + 4];
    const float* battn = (const float*)d_in[p + 5];
    const float* wproj = (const float*)d_in[p + 6];
    const float* bproj = (const float*)d_in[p + 7];
    const float* wfc   = (const float*)d_in[p + 8];
    const float* bfc   = (const float*)d_in[p + 9];
    const float* wfc2  = (const float*)d_in[p + 10];
    const float* bfc2  = (const float*)d_in[p + 11];
    float* out = (float*)d_out;

    float *x1, *qbuf, *att, *h, *x2, *ffn, *pm, *ps, *pa;
    cudaGetSymbolAddress((void**)&x1,   g_x1);
    cudaGetSymbolAddress((void**)&qbuf, g_q);
    cudaGetSymbolAddress((void**)&att,  g_att);
    cudaGetSymbolAddress((void**)&h,    g_h);
    cudaGetSymbolAddress((void**)&x2,   g_x2);
    cudaGetSymbolAddress((void**)&ffn,  g_ffn);
    cudaGetSymbolAddress((void**)&pm,   g_pm);
    cudaGetSymbolAddress((void**)&ps,   g_ps);
    cudaGetSymbolAddress((void**)&pa,   g_pa);

    cudaFuncSetAttribute(gemm_tc,
        cudaFuncAttributeMaxDynamicSharedMemorySize, GEMM_SMEM);

    // 1. ln1 rows (blocks 0-31) + q/h/ffn bias-inits (rest), one launch
    ln1_init_kernel<<<BATCH + 416, 256>>>(hidden, ln1g, ln1b, x1,
                                          qbuf, battn, h, bproj, ffn, bfc);
    // 2. q = x1 @ w_attn[:, :H] + b_attn[:H]   (16 x 27 = 432 CTAs -> 3/SM)
    gemm_tc<<<dim3(HDIM / TN, 27), 256, GEMM_SMEM>>>(x1, wattn, qbuf, HDIM, HDIM, QKV_N);
    // 3. attention (flash-decode, 32-way page split)
    attn_partial<<<dim3(BATCH, NHEADS, NSPLIT), 256>>>(qbuf, kv, bt, sl, pm, ps, pa);
    attn_combine<<<dim3(BATCH, NHEADS), 512>>>(pm, ps, pa, att);
    // 4. h += attn @ w_proj   (16 x 27 = 432 CTAs)
    gemm_tc<<<dim3(HDIM / TN, 27), 256, GEMM_SMEM>>>(att, wproj, h, HDIM, HDIM, HDIM);
    // 5. ln2 rows + out = h + b_fc2, one launch
    ln2_init_kernel<<<BATCH + 128, 256>>>(h, ln2g, ln2b, x2, out, bfc2);
    // 6. ffn += x2 @ w_fc   (64 x 7 = 448 CTAs)
    gemm_tc<<<dim3(DFF / TN, 7), 256, GEMM_SMEM>>>(x2, wfc, ffn, HDIM, DFF, DFF);
    // 6b. gelu(ffn) in place
    gelu_kernel<<<(BATCH * DFF / 4 + 255) / 256, 256>>>(ffn, BATCH * DFF / 4);
    // 7. out += gelu(ffn) @ w_fc2   (16 x 27 = 432 CTAs)
    gemm_tc<<<dim3(HDIM / TN, 27), 256, GEMM_SMEM>>>(ffn, wfc2, out, DFF, HDIM, HDIM);
}

// round 15
// speedup vs baseline: 1.1165x; 1.1165x over previous
#include <cuda_runtime.h>
#include <cuda_bf16.h>
#include <math.h>

// ---------------- constants ----------------
#define BATCH   32
#define HDIM    2048
#define NHEADS  16
#define HEADD   128
#define DFF     8192
#define QKV_N   (3*HDIM)   // 6144
#define MAXS    2048
#define MAXBLK  32
#define PAGE    64
#define NUMBLK  1024
#define NSPLIT  32
#define CHUNK   64         // MAXS / NSPLIT == one KV page
#define TKC     32         // gemm k-chunk
#define TN      128        // gemm n-tile
#define NSTAGE  3          // gemm pipeline stages

// ---------------- scratch (no allocs allowed) ----------------
__device__ float g_x1 [BATCH*HDIM];
__device__ float g_q  [BATCH*HDIM];      // only Q is needed (ref discards K,V cols)
__device__ float g_att[BATCH*HDIM];
__device__ float g_h  [BATCH*HDIM];
__device__ float g_x2 [BATCH*HDIM];
__device__ float g_ffn[BATCH*DFF];
__device__ float g_pm [BATCH*NHEADS*NSPLIT];
__device__ float g_ps [BATCH*NHEADS*NSPLIT];
__device__ float g_pa [BATCH*NHEADS*NSPLIT*HEADD];   // zero-init; empty splits stay 0

// ---------------- helpers ----------------
__device__ __forceinline__ float gelu_exact(float x) {
    return 0.5f * x * (1.0f + erff(x * 0.70710678118654752f));
}

// unbiased rounding to tf32 (A and W — biased truncation measured 2x worse err)
__device__ __forceinline__ unsigned rna_tf32(float x) {
    unsigned h;
    asm("cvt.rna.tf32.f32 %0, %1;" : "=r"(h) : "f"(x));
    return h;
}

__device__ __forceinline__ void mma_tf32(float d[4], const unsigned a[4],
                                         unsigned b0, unsigned b1) {
    asm volatile(
        "mma.sync.aligned.m16n8k8.row.col.f32.tf32.tf32.f32 "
        "{%0,%1,%2,%3}, {%4,%5,%6,%7}, {%8,%9}, {%0,%1,%2,%3};"
        : "+f"(d[0]), "+f"(d[1]), "+f"(d[2]), "+f"(d[3])
        : "r"(a[0]), "r"(a[1]), "r"(a[2]), "r"(a[3]), "r"(b0), "r"(b1));
}

__device__ __forceinline__ void cp_async16(void* smem, const void* g) {
    unsigned s = (unsigned)__cvta_generic_to_shared(smem);
    asm volatile("cp.async.cg.shared.global [%0], [%1], 16;" :: "r"(s), "l"(g));
}
__device__ __forceinline__ void cp_commit() {
    asm volatile("cp.async.commit_group;");
}
template<int N>
__device__ __forceinline__ void cp_wait() {
    asm volatile("cp.async.wait_group %0;" :: "n"(N));
}

// ---------------- LN body (one block, one row) ----------------
__device__ __forceinline__ void ln_row(
    const float* __restrict__ xr, const float* __restrict__ g,
    const float* __restrict__ b, float* __restrict__ yr)
{
    float s = 0.f, s2 = 0.f;
    for (int i = threadIdx.x; i < HDIM; i += 256) {
        float v = xr[i]; s += v; s2 += v * v;
    }
    __shared__ float sh[16];
    int lane = threadIdx.x & 31, w = threadIdx.x >> 5;
    #pragma unroll
    for (int o = 16; o; o >>= 1) {
        s  += __shfl_xor_sync(0xffffffffu, s,  o);
        s2 += __shfl_xor_sync(0xffffffffu, s2, o);
    }
    if (lane == 0) { sh[w] = s; sh[8 + w] = s2; }
    __syncthreads();
    if (threadIdx.x == 0) {
        float S = 0.f, S2 = 0.f;
        #pragma unroll
        for (int i = 0; i < 8; i++) { S += sh[i]; S2 += sh[8 + i]; }
        sh[0] = S; sh[1] = S2;
    }
    __syncthreads();
    float mu  = sh[0] * (1.0f / HDIM);
    float var = sh[1] * (1.0f / HDIM) - mu * mu;
    float inv = rsqrtf(var + 1e-5f);
    for (int i = threadIdx.x; i < HDIM; i += 256)
        yr[i] = (xr[i] - mu) * inv * g[i] + b[i];
}

// ---------------- phase 1: ln1 rows + init q/h/ffn (independent outputs) -----
__global__ void __launch_bounds__(256) ln1_init_kernel(
    const float* __restrict__ hidden,
    const float* __restrict__ ln1g, const float* __restrict__ ln1b,
    float* __restrict__ x1,
    float* __restrict__ q, const float* __restrict__ battn,
    float* __restrict__ h, const float* __restrict__ bproj,
    float* __restrict__ ffn, const float* __restrict__ bfc)
{
    if (blockIdx.x < BATCH) {
        int row = blockIdx.x;
        ln_row(hidden + row * HDIM, ln1g, ln1b, x1 + row * HDIM);
        return;
    }
    const int gix = blockIdx.x - BATCH;
    const int gnum = gridDim.x - BATCH;
    const int n1 = BATCH * HDIM;              // q
    const int n2 = n1 + BATCH * HDIM;         // h
    const int n3 = n2 + BATCH * DFF;          // ffn
    for (int i = gix * 256 + threadIdx.x; i < n3; i += gnum * 256) {
        if (i < n1) {
            q[i] = battn[i & (HDIM - 1)];
        } else if (i < n2) {
            int j = i - n1;
            h[j] = bproj[j & (HDIM - 1)] + hidden[j];
        } else {
            int j = i - n2;
            ffn[j] = bfc[j & (DFF - 1)];
        }
    }
}

// ---------------- phase 2: ln2 rows + out = h + b_fc2 (both depend on h) ----
__global__ void __launch_bounds__(256) ln2_init_kernel(
    const float* __restrict__ h,
    const float* __restrict__ ln2g, const float* __restrict__ ln2b,
    float* __restrict__ x2,
    float* __restrict__ out, const float* __restrict__ bfc2)
{
    if (blockIdx.x < BATCH) {
        int row = blockIdx.x;
        ln_row(h + row * HDIM, ln2g, ln2b, x2 + row * HDIM);
        return;
    }
    const int gix = blockIdx.x - BATCH;
    const int gnum = gridDim.x - BATCH;
    const int n = BATCH * HDIM;
    for (int i = gix * 256 + threadIdx.x; i < n; i += gnum * 256) {
        out[i] = h[i] + bfc2[i & (HDIM - 1)];
    }
}

// ---------------- elementwise gelu (in place, float4) ----------------
__global__ void __launch_bounds__(256) gelu_kernel(float* __restrict__ x, int n4)
{
    int i = blockIdx.x * 256 + threadIdx.x;
    if (i < n4) {
        float4 v = reinterpret_cast<float4*>(x)[i];
        v.x = gelu_exact(v.x); v.y = gelu_exact(v.y);
        v.z = gelu_exact(v.z); v.w = gelu_exact(v.w);
        reinterpret_cast<float4*>(x)[i] = v;
    }
}

// ---------------- tensor-core GEMM: C[32,Nout] += A[32,K] @ W[K,:Nout] -------
// 1xTF32, A and W rna-rounded (unbiased). 3-stage cp.async ring, 3 CTAs/SM,
// one barrier per chunk. ldW = W row stride (allows slicing w_attn to Q cols).
// Wave-balanced uneven split-K. atomicAdd into bias-preinitialized C.
#define WS_FL (TKC*136)
#define AS_FL (32*36)
#define GEMM_SMEM (NSTAGE*(WS_FL+AS_FL)*4)
__global__ void __launch_bounds__(256, 3) gemm_tc(
    const float* __restrict__ A, const float* __restrict__ W,
    float* __restrict__ C, int K, int Nout, int ldW)
{
    extern __shared__ float smp[];
    float (*Ws)[TKC][136] = reinterpret_cast<float(*)[TKC][136]>(smp);
    float (*As)[32][36]   = reinterpret_cast<float(*)[32][36]>(smp + NSTAGE * WS_FL);

    int tid = threadIdx.x;
    int lane = tid & 31, warp = tid >> 5;
    int m0 = (warp & 1) * 16;
    int n0w = (warp >> 1) * 32;
    int nblk = blockIdx.x * TN;

    int cchunks = K / TKC;
    int c0 = (int)(((long long)cchunks * blockIdx.y)       / gridDim.y);
    int c1 = (int)(((long long)cchunks * (blockIdx.y + 1)) / gridDim.y);
    int kbeg = c0 * TKC;
    int nchunk = c1 - c0;

    float acc[4][4] = {};

    int am = tid >> 3, ak = (tid & 7) * 4;   // A staging coords (1 seg/thread)
    int gr = lane >> 2, kq = lane & 3;       // fragment coords

    auto prefetch = [&](int chunk) {
        int kb = kbeg + chunk * TKC;
        int s = chunk % NSTAGE;
        cp_async16(&As[s][am][ak], &A[am * K + kb + ak]);
        #pragma unroll
        for (int it = 0; it < 4; ++it) {
            int idx = it * 256 + tid;
            int kk = idx >> 5, c4 = (idx & 31) * 4;
            cp_async16(&Ws[s][kk][c4], &W[(size_t)(kb + kk) * ldW + nblk + c4]);
        }
    };

    #pragma unroll
    for (int c = 0; c < NSTAGE - 1; ++c) {
        if (c < nchunk) prefetch(c);
        cp_commit();
    }

    for (int i = 0; i < nchunk; ++i) {
        cp_wait<NSTAGE - 2>();    // group i complete
        __syncthreads();          // all warps done with compute(i-1) and see stage i
        if (i + NSTAGE - 1 < nchunk) prefetch(i + NSTAGE - 1);
        cp_commit();
        int s = i % NSTAGE;
        #pragma unroll
        for (int ks = 0; ks < 4; ++ks) {
            int k0 = ks * 8;
            unsigned ah[4];
            ah[0] = rna_tf32(As[s][m0 + gr    ][k0 + kq    ]);
            ah[1] = rna_tf32(As[s][m0 + gr + 8][k0 + kq    ]);
            ah[2] = rna_tf32(As[s][m0 + gr    ][k0 + kq + 4]);
            ah[3] = rna_tf32(As[s][m0 + gr + 8][k0 + kq + 4]);
            #pragma unroll
            for (int nt = 0; nt < 4; ++nt) {
                int nb2 = n0w + nt * 8 + gr;
                unsigned bh0 = rna_tf32(Ws[s][k0 + kq    ][nb2]);
                unsigned bh1 = rna_tf32(Ws[s][k0 + kq + 4][nb2]);
                mma_tf32(acc[nt], ah, bh0, bh1);
            }
        }
    }

    int cq = (lane & 3) * 2;
    #pragma unroll
    for (int nt = 0; nt < 4; ++nt) {
        int col = nblk + n0w + nt * 8 + cq;
        atomicAdd(&C[(m0 + gr    ) * Nout + col    ], acc[nt][0]);
        atomicAdd(&C[(m0 + gr    ) * Nout + col + 1], acc[nt][1]);
        atomicAdd(&C[(m0 + gr + 8) * Nout + col    ], acc[nt][2]);
        atomicAdd(&C[(m0 + gr + 8) * Nout + col + 1], acc[nt][3]);
    }
}

// ---------------- attention partial: one block per (b,h,page) ----------------
__global__ void __launch_bounds__(256) attn_partial(
    const float* __restrict__ q, const float* __restrict__ kv,
    const int* __restrict__ bt, const int* __restrict__ sl,
    float* __restrict__ pm, float* __restrict__ ps, float* __restrict__ pa)
{
    int b = blockIdx.x, h = blockIdx.y, sp = blockIdx.z;
    int tid = threadIdx.x, lane = tid & 31, w = tid >> 5;
    int pidx = (b * NHEADS + h) * NSPLIT + sp;
    int seq = sl[b];
    int t0 = sp * CHUNK;
    if (t0 >= seq) {
        if (tid == 0) { pm[pidx] = -INFINITY; ps[pidx] = 0.f; }
        return;
    }
    int nt = seq - t0; if (nt > CHUNK) nt = CHUNK;

    __shared__ float qs[HEADD];
    __shared__ float sc[CHUNK];
    __shared__ int   rbs;              // page base (float index, < 2^31)
    __shared__ float sa[2][HEADD];

    if (tid < HEADD) qs[tid] = q[b * HDIM + h * HEADD + tid];
    if (tid == 0)
        rbs = bt[b * MAXBLK + sp] * (PAGE * NHEADS * HEADD) + h * HEADD;
    __syncthreads();
    int rb = rbs;

    const float scale = 0.08838834764831845f;  // 1/sqrt(128)
    float4 qx = reinterpret_cast<const float4*>(qs)[lane];

    // pass 1: scores. 4 tokens/warp/iter (loads clamped to page row 63 — always
    // resident; stores guarded by nt). Interleaved shfl chains pipeline.
    for (int tb = w * 4; tb < nt; tb += 32) {
        int u1 = min(tb + 1, 63), u2 = min(tb + 2, 63), u3 = min(tb + 3, 63);
        const float* base = kv + rb;
        float4 ka = reinterpret_cast<const float4*>(base + tb * (NHEADS * HEADD))[lane];
        float4 kb2 = reinterpret_cast<const float4*>(base + u1 * (NHEADS * HEADD))[lane];
        float4 kc2 = reinterpret_cast<const float4*>(base + u2 * (NHEADS * HEADD))[lane];
        float4 kd2 = reinterpret_cast<const float4*>(base + u3 * (NHEADS * HEADD))[lane];
        float d0 = ka.x  * qx.x + ka.y  * qx.y + ka.z  * qx.z + ka.w  * qx.w;
        float d1 = kb2.x * qx.x + kb2.y * qx.y + kb2.z * qx.z + kb2.w * qx.w;
        float d2 = kc2.x * qx.x + kc2.y * qx.y + kc2.z * qx.z + kc2.w * qx.w;
        float d3 = kd2.x * qx.x + kd2.y * qx.y + kd2.z * qx.z + kd2.w * qx.w;
        #pragma unroll
        for (int o = 16; o; o >>= 1) {
            d0 += __shfl_xor_sync(0xffffffffu, d0, o);
            d1 += __shfl_xor_sync(0xffffffffu, d1, o);
            d2 += __shfl_xor_sync(0xffffffffu, d2, o);
            d3 += __shfl_xor_sync(0xffffffffu, d3, o);
        }
        if (lane == 0) {
            sc[tb] = d0 * scale;
            if (tb + 1 < nt) sc[tb + 1] = d1 * scale;
            if (tb + 2 < nt) sc[tb + 2] = d2 * scale;
            if (tb + 3 < nt) sc[tb + 3] = d3 * scale;
        }
    }
    __syncthreads();

    // softmax stats in ONE warp (nt <= 64 -> 2 values/lane), then one barrier.
    if (w == 0) {
        float v0 = (lane      < nt) ? sc[lane]      : -INFINITY;
        float v1 = (lane + 32 < nt) ? sc[lane + 32] : -INFINITY;
        float m = fmaxf(v0, v1);
        #pragma unroll
        for (int o = 16; o; o >>= 1) m = fmaxf(m, __shfl_xor_sync(0xffffffffu, m, o));
        float e0 = (lane      < nt) ? __expf(v0 - m) : 0.f;
        float e1 = (lane + 32 < nt) ? __expf(v1 - m) : 0.f;
        if (lane      < nt) sc[lane]      = e0;
        if (lane + 32 < nt) sc[lane + 32] = e1;
        float s = e0 + e1;
        #pragma unroll
        for (int o = 16; o; o >>= 1) s += __shfl_xor_sync(0xffffffffu, s, o);
        if (lane == 0) { pm[pidx] = m; ps[pidx] = s; }
    }
    __syncthreads();

    // pass 2: unnormalized weighted V. 2 halves x 4-way unroll.
    int d = tid & 127, half = tid >> 7;
    const float* Vb = kv + (size_t)NUMBLK * PAGE * NHEADS * HEADD;
    float a0 = 0.f, a1 = 0.f, a2 = 0.f, a3 = 0.f;
    int t = half;
    for (; t + 6 < nt; t += 8) {
        const float* v0 = Vb + rb + (t    ) * (NHEADS * HEADD);
        const float* v1 = Vb + rb + (t + 2) * (NHEADS * HEADD);
        const float* v2 = Vb + rb + (t + 4) * (NHEADS * HEADD);
        const float* v3 = Vb + rb + (t + 6) * (NHEADS * HEADD);
        a0 += sc[t    ] * v0[d];
        a1 += sc[t + 2] * v1[d];
        a2 += sc[t + 4] * v2[d];
        a3 += sc[t + 6] * v3[d];
    }
    for (; t < nt; t += 2) {
        const float* vr = Vb + rb + t * (NHEADS * HEADD);
        a0 += sc[t] * vr[d];
    }
    sa[half][d] = (a0 + a1) + (a2 + a3);
    __syncthreads();
    if (tid < HEADD) pa[(size_t)pidx * HEADD + tid] = sa[0][tid] + sa[1][tid];
}

// ---------------- attention combine v3: one block per (b,h), 256 threads ----
// Warp 0 computes M, den, and the 32 softmax weights ONCE (32 expf/block,
// was ~20k in v2). 256 threads = 2 split-halves x 128 dims; each thread does
// 16 independent LDG+FFMA (4 accumulators, no MUFU, low regs).
// pa of empty splits is statically zero -> wgt 0 * 0 is safe.
__global__ void __launch_bounds__(256) attn_combine(
    const float* __restrict__ pm, const float* __restrict__ ps,
    const float* __restrict__ pa, float* __restrict__ out)
{
    int b = blockIdx.x, h = blockIdx.y;
    int idx = b * NHEADS + h;
    int tid = threadIdx.x;
    int d = tid & 127, g = tid >> 7;          // g in {0,1}: splits g*16..g*16+15
    __shared__ float wgt[NSPLIT];
    __shared__ float dens;
    __shared__ float part[2][HEADD];

    if (tid < 32) {
        float mi = pm[idx * NSPLIT + tid];
        float si = ps[idx * NSPLIT + tid];
        float mv = (si > 0.f) ? mi : -INFINITY;
        float M = mv;
        #pragma unroll
        for (int o = 16; o; o >>= 1) M = fmaxf(M, __shfl_xor_sync(0xffffffffu, M, o));
        float e = (si > 0.f) ? __expf(mi - M) : 0.f;
        float den = e * si;
        #pragma unroll
        for (int o = 16; o; o >>= 1) den += __shfl_xor_sync(0xffffffffu, den, o);
        wgt[tid] = e;
        if (tid == 0) dens = den;
    }
    __syncthreads();

    const float* pab = pa + ((size_t)idx * NSPLIT + g * 16) * HEADD + d;
    float a0 = 0.f, a1 = 0.f, a2 = 0.f, a3 = 0.f;
    #pragma unroll
    for (int k = 0; k < 16; k += 4) {
        int i = g * 16 + k;
        a0 += wgt[i    ] * pab[(k    ) * HEADD];
        a1 += wgt[i + 1] * pab[(k + 1) * HEADD];
        a2 += wgt[i + 2] * pab[(k + 2) * HEADD];
        a3 += wgt[i + 3] * pab[(k + 3) * HEADD];
    }
    part[g][d] = (a0 + a1) + (a2 + a3);
    __syncthreads();
    if (g == 0)
        out[b * HDIM + h * HEADD + d] = (part[0][d] + part[1][d]) / dens;
}

// ---------------- host launcher ----------------
extern "C" void kernel_launch(void* const* d_in, const int* in_sizes, int n_in,
                              void* d_out, int out_size)
{
    const float* hidden = (const float*)d_in[0];
    const float* kv     = (const float*)d_in[1];
    const int*   bt     = (const int*)d_in[2];
    const int*   sl     = (const int*)d_in[3];
    int p = (n_in > 4 && in_sizes[4] == 1) ? 5 : 4;  // skip max_seq_len if present
    const float* ln1g  = (const float*)d_in[p + 0];
    const float* ln1b  = (const float*)d_in[p + 1];
    const float* ln2g  = (const float*)d_in[p + 2];
    const float* ln2b  = (const float*)d_in[p + 3];
    const float* wattn = (const float*)d_in[p + 4];
    const float* battn = (const float*)d_in[p + 5];
    const float* wproj = (const float*)d_in[p + 6];
    const float* bproj = (const float*)d_in[p + 7];
    const float* wfc   = (const float*)d_in[p + 8];
    const float* bfc   = (const float*)d_in[p + 9];
    const float* wfc2  = (const float*)d_in[p + 10];
    const float* bfc2  = (const float*)d_in[p + 11];
    float* out = (float*)d_out;

    float *x1, *qbuf, *att, *h, *x2, *ffn, *pm, *ps, *pa;
    cudaGetSymbolAddress((void**)&x1,   g_x1);
    cudaGetSymbolAddress((void**)&qbuf, g_q);
    cudaGetSymbolAddress((void**)&att,  g_att);
    cudaGetSymbolAddress((void**)&h,    g_h);
    cudaGetSymbolAddress((void**)&x2,   g_x2);
    cudaGetSymbolAddress((void**)&ffn,  g_ffn);
    cudaGetSymbolAddress((void**)&pm,   g_pm);
    cudaGetSymbolAddress((void**)&ps,   g_ps);
    cudaGetSymbolAddress((void**)&pa,   g_pa);

    cudaFuncSetAttribute(gemm_tc,
        cudaFuncAttributeMaxDynamicSharedMemorySize, GEMM_SMEM);

    // 1. ln1 rows (blocks 0-31) + q/h/ffn bias-inits (rest), one launch
    ln1_init_kernel<<<BATCH + 416, 256>>>(hidden, ln1g, ln1b, x1,
                                          qbuf, battn, h, bproj, ffn, bfc);
    // 2. q = x1 @ w_attn[:, :H] + b_attn[:H]   (16 x 27 = 432 CTAs -> 3/SM)
    gemm_tc<<<dim3(HDIM / TN, 27), 256, GEMM_SMEM>>>(x1, wattn, qbuf, HDIM, HDIM, QKV_N);
    // 3. attention (flash-decode, 32-way page split)
    attn_partial<<<dim3(BATCH, NHEADS, NSPLIT), 256>>>(qbuf, kv, bt, sl, pm, ps, pa);
    attn_combine<<<dim3(BATCH, NHEADS), 256>>>(pm, ps, pa, att);
    // 4. h += attn @ w_proj   (16 x 27 = 432 CTAs)
    gemm_tc<<<dim3(HDIM / TN, 27), 256, GEMM_SMEM>>>(att, wproj, h, HDIM, HDIM, HDIM);
    // 5. ln2 rows + out = h + b_fc2, one launch
    ln2_init_kernel<<<BATCH + 128, 256>>>(h, ln2g, ln2b, x2, out, bfc2);
    // 6. ffn += x2 @ w_fc   (64 x 7 = 448 CTAs)
    gemm_tc<<<dim3(DFF / TN, 7), 256, GEMM_SMEM>>>(x2, wfc, ffn, HDIM, DFF, DFF);
    // 6b. gelu(ffn) in place
    gelu_kernel<<<(BATCH * DFF / 4 + 255) / 256, 256>>>(ffn, BATCH * DFF / 4);
    // 7. out += gelu(ffn) @ w_fc2   (16 x 27 = 432 CTAs)
    gemm_tc<<<dim3(HDIM / TN, 27), 256, GEMM_SMEM>>>(ffn, wfc2, out, DFF, HDIM, HDIM);
}

// round 16
// speedup vs baseline: 1.1252x; 1.0077x over previous
#include <cuda_runtime.h>
#include <cuda_bf16.h>
#include <math.h>

// ---------------- constants ----------------
#define BATCH   32
#define HDIM    2048
#define NHEADS  16
#define HEADD   128
#define DFF     8192
#define QKV_N   (3*HDIM)   // 6144
#define MAXS    2048
#define MAXBLK  32
#define PAGE    64
#define NUMBLK  1024
#define NSPLIT  32
#define CHUNK   64         // MAXS / NSPLIT == one KV page
#define TKC     32         // gemm k-chunk
#define TN      128        // gemm n-tile
#define NSTAGE  3          // gemm pipeline stages

// ---------------- scratch (no allocs allowed) ----------------
__device__ float g_x1 [BATCH*HDIM];
__device__ float g_q  [BATCH*HDIM];      // only Q is needed (ref discards K,V cols)
__device__ float g_att[BATCH*HDIM];
__device__ float g_h  [BATCH*HDIM];
__device__ float g_x2 [BATCH*HDIM];
__device__ float g_ffn[BATCH*DFF];
__device__ float g_pm [BATCH*NHEADS*NSPLIT];
__device__ float g_ps [BATCH*NHEADS*NSPLIT];
__device__ float g_pa [BATCH*NHEADS*NSPLIT*HEADD];   // zero-init; empty splits stay 0

// ---------------- helpers ----------------
__device__ __forceinline__ float gelu_exact(float x) {
    return 0.5f * x * (1.0f + erff(x * 0.70710678118654752f));
}

// unbiased rounding to tf32 (A and W — biased truncation measured 2x worse err)
__device__ __forceinline__ unsigned rna_tf32(float x) {
    unsigned h;
    asm("cvt.rna.tf32.f32 %0, %1;" : "=r"(h) : "f"(x));
    return h;
}

__device__ __forceinline__ void mma_tf32(float d[4], const unsigned a[4],
                                         unsigned b0, unsigned b1) {
    asm volatile(
        "mma.sync.aligned.m16n8k8.row.col.f32.tf32.tf32.f32 "
        "{%0,%1,%2,%3}, {%4,%5,%6,%7}, {%8,%9}, {%0,%1,%2,%3};"
        : "+f"(d[0]), "+f"(d[1]), "+f"(d[2]), "+f"(d[3])
        : "r"(a[0]), "r"(a[1]), "r"(a[2]), "r"(a[3]), "r"(b0), "r"(b1));
}

__device__ __forceinline__ void cp_async16(void* smem, const void* g) {
    unsigned s = (unsigned)__cvta_generic_to_shared(smem);
    asm volatile("cp.async.cg.shared.global [%0], [%1], 16;" :: "r"(s), "l"(g));
}
__device__ __forceinline__ void cp_commit() {
    asm volatile("cp.async.commit_group;");
}
template<int N>
__device__ __forceinline__ void cp_wait() {
    asm volatile("cp.async.wait_group %0;" :: "n"(N));
}

// vector reduction: 2 contiguous fp32 adds in one RED (sm_90+)
__device__ __forceinline__ void red_add_v2(float* p, float a, float b) {
    asm volatile("red.global.add.v2.f32 [%0], {%1, %2};"
                 :: "l"(p), "f"(a), "f"(b) : "memory");
}

// ---------------- LN body (one block, one row) ----------------
__device__ __forceinline__ void ln_row(
    const float* __restrict__ xr, const float* __restrict__ g,
    const float* __restrict__ b, float* __restrict__ yr)
{
    float s = 0.f, s2 = 0.f;
    for (int i = threadIdx.x; i < HDIM; i += 256) {
        float v = xr[i]; s += v; s2 += v * v;
    }
    __shared__ float sh[16];
    int lane = threadIdx.x & 31, w = threadIdx.x >> 5;
    #pragma unroll
    for (int o = 16; o; o >>= 1) {
        s  += __shfl_xor_sync(0xffffffffu, s,  o);
        s2 += __shfl_xor_sync(0xffffffffu, s2, o);
    }
    if (lane == 0) { sh[w] = s; sh[8 + w] = s2; }
    __syncthreads();
    if (threadIdx.x == 0) {
        float S = 0.f, S2 = 0.f;
        #pragma unroll
        for (int i = 0; i < 8; i++) { S += sh[i]; S2 += sh[8 + i]; }
        sh[0] = S; sh[1] = S2;
    }
    __syncthreads();
    float mu  = sh[0] * (1.0f / HDIM);
    float var = sh[1] * (1.0f / HDIM) - mu * mu;
    float inv = rsqrtf(var + 1e-5f);
    for (int i = threadIdx.x; i < HDIM; i += 256)
        yr[i] = (xr[i] - mu) * inv * g[i] + b[i];
}

// ---------------- phase 1: ln1 rows + init q/h/ffn (independent outputs) -----
__global__ void __launch_bounds__(256) ln1_init_kernel(
    const float* __restrict__ hidden,
    const float* __restrict__ ln1g, const float* __restrict__ ln1b,
    float* __restrict__ x1,
    float* __restrict__ q, const float* __restrict__ battn,
    float* __restrict__ h, const float* __restrict__ bproj,
    float* __restrict__ ffn, const float* __restrict__ bfc)
{
    if (blockIdx.x < BATCH) {
        int row = blockIdx.x;
        ln_row(hidden + row * HDIM, ln1g, ln1b, x1 + row * HDIM);
        return;
    }
    const int gix = blockIdx.x - BATCH;
    const int gnum = gridDim.x - BATCH;
    const int n1 = BATCH * HDIM;              // q
    const int n2 = n1 + BATCH * HDIM;         // h
    const int n3 = n2 + BATCH * DFF;          // ffn
    for (int i = gix * 256 + threadIdx.x; i < n3; i += gnum * 256) {
        if (i < n1) {
            q[i] = battn[i & (HDIM - 1)];
        } else if (i < n2) {
            int j = i - n1;
            h[j] = bproj[j & (HDIM - 1)] + hidden[j];
        } else {
            int j = i - n2;
            ffn[j] = bfc[j & (DFF - 1)];
        }
    }
}

// ---------------- phase 2: ln2 rows + out = h + b_fc2 (both depend on h) ----
__global__ void __launch_bounds__(256) ln2_init_kernel(
    const float* __restrict__ h,
    const float* __restrict__ ln2g, const float* __restrict__ ln2b,
    float* __restrict__ x2,
    float* __restrict__ out, const float* __restrict__ bfc2)
{
    if (blockIdx.x < BATCH) {
        int row = blockIdx.x;
        ln_row(h + row * HDIM, ln2g, ln2b, x2 + row * HDIM);
        return;
    }
    const int gix = blockIdx.x - BATCH;
    const int gnum = gridDim.x - BATCH;
    const int n = BATCH * HDIM;
    for (int i = gix * 256 + threadIdx.x; i < n; i += gnum * 256) {
        out[i] = h[i] + bfc2[i & (HDIM - 1)];
    }
}

// ---------------- elementwise gelu (in place, float4) ----------------
__global__ void __launch_bounds__(256) gelu_kernel(float* __restrict__ x, int n4)
{
    int i = blockIdx.x * 256 + threadIdx.x;
    if (i < n4) {
        float4 v = reinterpret_cast<float4*>(x)[i];
        v.x = gelu_exact(v.x); v.y = gelu_exact(v.y);
        v.z = gelu_exact(v.z); v.w = gelu_exact(v.w);
        reinterpret_cast<float4*>(x)[i] = v;
    }
}

// ---------------- tensor-core GEMM: C[32,Nout] += A[32,K] @ W[K,:Nout] -------
// 1xTF32, A and W rna-rounded (unbiased). 3-stage cp.async ring, 3 CTAs/SM,
// one barrier per chunk. ldW = W row stride (allows slicing w_attn to Q cols).
// Wave-balanced uneven split-K. red.v2 into bias-preinitialized C (halves the
// atomic instruction count vs scalar atomicAdd).
#define WS_FL (TKC*136)
#define AS_FL (32*36)
#define GEMM_SMEM (NSTAGE*(WS_FL+AS_FL)*4)
__global__ void __launch_bounds__(256, 3) gemm_tc(
    const float* __restrict__ A, const float* __restrict__ W,
    float* __restrict__ C, int K, int Nout, int ldW)
{
    extern __shared__ float smp[];
    float (*Ws)[TKC][136] = reinterpret_cast<float(*)[TKC][136]>(smp);
    float (*As)[32][36]   = reinterpret_cast<float(*)[32][36]>(smp + NSTAGE * WS_FL);

    int tid = threadIdx.x;
    int lane = tid & 31, warp = tid >> 5;
    int m0 = (warp & 1) * 16;
    int n0w = (warp >> 1) * 32;
    int nblk = blockIdx.x * TN;

    int cchunks = K / TKC;
    int c0 = (int)(((long long)cchunks * blockIdx.y)       / gridDim.y);
    int c1 = (int)(((long long)cchunks * (blockIdx.y + 1)) / gridDim.y);
    int kbeg = c0 * TKC;
    int nchunk = c1 - c0;

    float acc[4][4] = {};

    int am = tid >> 3, ak = (tid & 7) * 4;   // A staging coords (1 seg/thread)
    int gr = lane >> 2, kq = lane & 3;       // fragment coords

    auto prefetch = [&](int chunk) {
        int kb = kbeg + chunk * TKC;
        int s = chunk % NSTAGE;
        cp_async16(&As[s][am][ak], &A[am * K + kb + ak]);
        #pragma unroll
        for (int it = 0; it < 4; ++it) {
            int idx = it * 256 + tid;
            int kk = idx >> 5, c4 = (idx & 31) * 4;
            cp_async16(&Ws[s][kk][c4], &W[(size_t)(kb + kk) * ldW + nblk + c4]);
        }
    };

    #pragma unroll
    for (int c = 0; c < NSTAGE - 1; ++c) {
        if (c < nchunk) prefetch(c);
        cp_commit();
    }

    for (int i = 0; i < nchunk; ++i) {
        cp_wait<NSTAGE - 2>();    // group i complete
        __syncthreads();          // all warps done with compute(i-1) and see stage i
        if (i + NSTAGE - 1 < nchunk) prefetch(i + NSTAGE - 1);
        cp_commit();
        int s = i % NSTAGE;
        #pragma unroll
        for (int ks = 0; ks < 4; ++ks) {
            int k0 = ks * 8;
            unsigned ah[4];
            ah[0] = rna_tf32(As[s][m0 + gr    ][k0 + kq    ]);
            ah[1] = rna_tf32(As[s][m0 + gr + 8][k0 + kq    ]);
            ah[2] = rna_tf32(As[s][m0 + gr    ][k0 + kq + 4]);
            ah[3] = rna_tf32(As[s][m0 + gr + 8][k0 + kq + 4]);
            #pragma unroll
            for (int nt = 0; nt < 4; ++nt) {
                int nb2 = n0w + nt * 8 + gr;
                unsigned bh0 = rna_tf32(Ws[s][k0 + kq    ][nb2]);
                unsigned bh1 = rna_tf32(Ws[s][k0 + kq + 4][nb2]);
                mma_tf32(acc[nt], ah, bh0, bh1);
            }
        }
    }

    // writeout: fragment cols (cq, cq+1) are contiguous & 8B-aligned -> red.v2
    int cq = (lane & 3) * 2;
    #pragma unroll
    for (int nt = 0; nt < 4; ++nt) {
        int col = nblk + n0w + nt * 8 + cq;
        red_add_v2(&C[(m0 + gr    ) * Nout + col], acc[nt][0], acc[nt][1]);
        red_add_v2(&C[(m0 + gr + 8) * Nout + col], acc[nt][2], acc[nt][3]);
    }
}

// ---------------- attention partial: one block per (b,h,page) ----------------
__global__ void __launch_bounds__(256) attn_partial(
    const float* __restrict__ q, const float* __restrict__ kv,
    const int* __restrict__ bt, const int* __restrict__ sl,
    float* __restrict__ pm, float* __restrict__ ps, float* __restrict__ pa)
{
    int b = blockIdx.x, h = blockIdx.y, sp = blockIdx.z;
    int tid = threadIdx.x, lane = tid & 31, w = tid >> 5;
    int pidx = (b * NHEADS + h) * NSPLIT + sp;
    int seq = sl[b];
    int t0 = sp * CHUNK;
    if (t0 >= seq) {
        if (tid == 0) { pm[pidx] = -INFINITY; ps[pidx] = 0.f; }
        return;
    }
    int nt = seq - t0; if (nt > CHUNK) nt = CHUNK;

    __shared__ float qs[HEADD];
    __shared__ float sc[CHUNK];
    __shared__ int   rbs;              // page base (float index, < 2^31)
    __shared__ float sa[2][HEADD];

    if (tid < HEADD) qs[tid] = q[b * HDIM + h * HEADD + tid];
    if (tid == 0)
        rbs = bt[b * MAXBLK + sp] * (PAGE * NHEADS * HEADD) + h * HEADD;
    __syncthreads();
    int rb = rbs;

    const float scale = 0.08838834764831845f;  // 1/sqrt(128)
    float4 qx = reinterpret_cast<const float4*>(qs)[lane];

    // pass 1: scores. 4 tokens/warp/iter (loads clamped to page row 63 — always
    // resident; stores guarded by nt). Interleaved shfl chains pipeline.
    for (int tb = w * 4; tb < nt; tb += 32) {
        int u1 = min(tb + 1, 63), u2 = min(tb + 2, 63), u3 = min(tb + 3, 63);
        const float* base = kv + rb;
        float4 ka = reinterpret_cast<const float4*>(base + tb * (NHEADS * HEADD))[lane];
        float4 kb2 = reinterpret_cast<const float4*>(base + u1 * (NHEADS * HEADD))[lane];
        float4 kc2 = reinterpret_cast<const float4*>(base + u2 * (NHEADS * HEADD))[lane];
        float4 kd2 = reinterpret_cast<const float4*>(base + u3 * (NHEADS * HEADD))[lane];
        float d0 = ka.x  * qx.x + ka.y  * qx.y + ka.z  * qx.z + ka.w  * qx.w;
        float d1 = kb2.x * qx.x + kb2.y * qx.y + kb2.z * qx.z + kb2.w * qx.w;
        float d2 = kc2.x * qx.x + kc2.y * qx.y + kc2.z * qx.z + kc2.w * qx.w;
        float d3 = kd2.x * qx.x + kd2.y * qx.y + kd2.z * qx.z + kd2.w * qx.w;
        #pragma unroll
        for (int o = 16; o; o >>= 1) {
            d0 += __shfl_xor_sync(0xffffffffu, d0, o);
            d1 += __shfl_xor_sync(0xffffffffu, d1, o);
            d2 += __shfl_xor_sync(0xffffffffu, d2, o);
            d3 += __shfl_xor_sync(0xffffffffu, d3, o);
        }
        if (lane == 0) {
            sc[tb] = d0 * scale;
            if (tb + 1 < nt) sc[tb + 1] = d1 * scale;
            if (tb + 2 < nt) sc[tb + 2] = d2 * scale;
            if (tb + 3 < nt) sc[tb + 3] = d3 * scale;
        }
    }
    __syncthreads();

    // softmax stats in ONE warp (nt <= 64 -> 2 values/lane), then one barrier.
    if (w == 0) {
        float v0 = (lane      < nt) ? sc[lane]      : -INFINITY;
        float v1 = (lane + 32 < nt) ? sc[lane + 32] : -INFINITY;
        float m = fmaxf(v0, v1);
        #pragma unroll
        for (int o = 16; o; o >>= 1) m = fmaxf(m, __shfl_xor_sync(0xffffffffu, m, o));
        float e0 = (lane      < nt) ? __expf(v0 - m) : 0.f;
        float e1 = (lane + 32 < nt) ? __expf(v1 - m) : 0.f;
        if (lane      < nt) sc[lane]      = e0;
        if (lane + 32 < nt) sc[lane + 32] = e1;
        float s = e0 + e1;
        #pragma unroll
        for (int o = 16; o; o >>= 1) s += __shfl_xor_sync(0xffffffffu, s, o);
        if (lane == 0) { pm[pidx] = m; ps[pidx] = s; }
    }
    __syncthreads();

    // pass 2: unnormalized weighted V. 2 halves x 4-way unroll.
    int d = tid & 127, half = tid >> 7;
    const float* Vb = kv + (size_t)NUMBLK * PAGE * NHEADS * HEADD;
    float a0 = 0.f, a1 = 0.f, a2 = 0.f, a3 = 0.f;
    int t = half;
    for (; t + 6 < nt; t += 8) {
        const float* v0 = Vb + rb + (t    ) * (NHEADS * HEADD);
        const float* v1 = Vb + rb + (t + 2) * (NHEADS * HEADD);
        const float* v2 = Vb + rb + (t + 4) * (NHEADS * HEADD);
        const float* v3 = Vb + rb + (t + 6) * (NHEADS * HEADD);
        a0 += sc[t    ] * v0[d];
        a1 += sc[t + 2] * v1[d];
        a2 += sc[t + 4] * v2[d];
        a3 += sc[t + 6] * v3[d];
    }
    for (; t < nt; t += 2) {
        const float* vr = Vb + rb + t * (NHEADS * HEADD);
        a0 += sc[t] * vr[d];
    }
    sa[half][d] = (a0 + a1) + (a2 + a3);
    __syncthreads();
    if (tid < HEADD) pa[(size_t)pidx * HEADD + tid] = sa[0][tid] + sa[1][tid];
}

// ---------------- attention combine v3: one block per (b,h), 256 threads ----
// Warp 0 computes M, den, and the 32 softmax weights ONCE (32 expf/block).
// 256 threads = 2 split-halves x 128 dims; each thread does 16 independent
// LDG+FFMA (4 accumulators, no MUFU, low regs). Empty-split pa is zero.
__global__ void __launch_bounds__(256) attn_combine(
    const float* __restrict__ pm, const float* __restrict__ ps,
    const float* __restrict__ pa, float* __restrict__ out)
{
    int b = blockIdx.x, h = blockIdx.y;
    int idx = b * NHEADS + h;
    int tid = threadIdx.x;
    int d = tid & 127, g = tid >> 7;          // g in {0,1}: splits g*16..g*16+15
    __shared__ float wgt[NSPLIT];
    __shared__ float dens;
    __shared__ float part[2][HEADD];

    if (tid < 32) {
        float mi = pm[idx * NSPLIT + tid];
        float si = ps[idx * NSPLIT + tid];
        float mv = (si > 0.f) ? mi : -INFINITY;
        float M = mv;
        #pragma unroll
        for (int o = 16; o; o >>= 1) M = fmaxf(M, __shfl_xor_sync(0xffffffffu, M, o));
        float e = (si > 0.f) ? __expf(mi - M) : 0.f;
        float den = e * si;
        #pragma unroll
        for (int o = 16; o; o >>= 1) den += __shfl_xor_sync(0xffffffffu, den, o);
        wgt[tid] = e;
        if (tid == 0) dens = den;
    }
    __syncthreads();

    const float* pab = pa + ((size_t)idx * NSPLIT + g * 16) * HEADD + d;
    float a0 = 0.f, a1 = 0.f, a2 = 0.f, a3 = 0.f;
    #pragma unroll
    for (int k = 0; k < 16; k += 4) {
        int i = g * 16 + k;
        a0 += wgt[i    ] * pab[(k    ) * HEADD];
        a1 += wgt[i + 1] * pab[(k + 1) * HEADD];
        a2 += wgt[i + 2] * pab[(k + 2) * HEADD];
        a3 += wgt[i + 3] * pab[(k + 3) * HEADD];
    }
    part[g][d] = (a0 + a1) + (a2 + a3);
    __syncthreads();
    if (g == 0)
        out[b * HDIM + h * HEADD + d] = (part[0][d] + part[1][d]) / dens;
}

// ---------------- host launcher ----------------
extern "C" void kernel_launch(void* const* d_in, const int* in_sizes, int n_in,
                              void* d_out, int out_size)
{
    const float* hidden = (const float*)d_in[0];
    const float* kv     = (const float*)d_in[1];
    const int*   bt     = (const int*)d_in[2];
    const int*   sl     = (const int*)d_in[3];
    int p = (n_in > 4 && in_sizes[4] == 1) ? 5 : 4;  // skip max_seq_len if present
    const float* ln1g  = (const float*)d_in[p + 0];
    const float* ln1b  = (const float*)d_in[p + 1];
    const float* ln2g  = (const float*)d_in[p + 2];
    const float* ln2b  = (const float*)d_in[p + 3];
    const float* wattn = (const float*)d_in[p + 4];
    const float* battn = (const float*)d_in[p + 5];
    const float* wproj = (const float*)d_in[p + 6];
    const float* bproj = (const float*)d_in[p + 7];
    const float* wfc   = (const float*)d_in[p + 8];
    const float* bfc   = (const float*)d_in[p + 9];
    const float* wfc2  = (const float*)d_in[p + 10];
    const float* bfc2  = (const float*)d_in[p + 11];
    float* out = (float*)d_out;

    float *x1, *qbuf, *att, *h, *x2, *ffn, *pm, *ps, *pa;
    cudaGetSymbolAddress((void**)&x1,   g_x1);
    cudaGetSymbolAddress((void**)&qbuf, g_q);
    cudaGetSymbolAddress((void**)&att,  g_att);
    cudaGetSymbolAddress((void**)&h,    g_h);
    cudaGetSymbolAddress((void**)&x2,   g_x2);
    cudaGetSymbolAddress((void**)&ffn,  g_ffn);
    cudaGetSymbolAddress((void**)&pm,   g_pm);
    cudaGetSymbolAddress((void**)&ps,   g_ps);
    cudaGetSymbolAddress((void**)&pa,   g_pa);

    cudaFuncSetAttribute(gemm_tc,
        cudaFuncAttributeMaxDynamicSharedMemorySize, GEMM_SMEM);

    // 1. ln1 rows (blocks 0-31) + q/h/ffn bias-inits (rest), one launch
    ln1_init_kernel<<<BATCH + 416, 256>>>(hidden, ln1g, ln1b, x1,
                                          qbuf, battn, h, bproj, ffn, bfc);
    // 2. q = x1 @ w_attn[:, :H] + b_attn[:H]   (16 x 27 = 432 CTAs -> 3/SM)
    gemm_tc<<<dim3(HDIM / TN, 27), 256, GEMM_SMEM>>>(x1, wattn, qbuf, HDIM, HDIM, QKV_N);
    // 3. attention (flash-decode, 32-way page split)
    attn_partial<<<dim3(BATCH, NHEADS, NSPLIT), 256>>>(qbuf, kv, bt, sl, pm, ps, pa);
    attn_combine<<<dim3(BATCH, NHEADS), 256>>>(pm, ps, pa, att);
    // 4. h += attn @ w_proj   (16 x 27 = 432 CTAs)
    gemm_tc<<<dim3(HDIM / TN, 27), 256, GEMM_SMEM>>>(att, wproj, h, HDIM, HDIM, HDIM);
    // 5. ln2 rows + out = h + b_fc2, one launch
    ln2_init_kernel<<<BATCH + 128, 256>>>(h, ln2g, ln2b, x2, out, bfc2);
    // 6. ffn += x2 @ w_fc   (64 x 7 = 448 CTAs)
    gemm_tc<<<dim3(DFF / TN, 7), 256, GEMM_SMEM>>>(x2, wfc, ffn, HDIM, DFF, DFF);
    // 6b. gelu(ffn) in place
    gelu_kernel<<<(BATCH * DFF / 4 + 255) / 256, 256>>>(ffn, BATCH * DFF / 4);
    // 7. out += gelu(ffn) @ w_fc2   (16 x 27 = 432 CTAs)
    gemm_tc<<<dim3(HDIM / TN, 27), 256, GEMM_SMEM>>>(ffn, wfc2, out, DFF, HDIM, HDIM);
}

// round 17
// speedup vs baseline: 1.1958x; 1.0627x over previous
#include <cuda_runtime.h>
#include <cuda_bf16.h>
#include <math.h>

// ---------------- constants ----------------
#define BATCH   32
#define HDIM    2048
#define NHEADS  16
#define HEADD   128
#define DFF     8192
#define QKV_N   (3*HDIM)   // 6144
#define MAXS    2048
#define MAXBLK  32
#define PAGE    64
#define NUMBLK  1024
#define NSPLIT  32
#define CHUNK   64         // MAXS / NSPLIT == one KV page
#define TKC     32         // gemm k-chunk
#define TN      128        // gemm n-tile
#define NSTAGE  3          // gemm pipeline stages

// ---------------- scratch (no allocs allowed) ----------------
__device__ float g_x1 [BATCH*HDIM];
__device__ float g_q  [BATCH*HDIM];      // only Q is needed (ref discards K,V cols)
__device__ float g_att[BATCH*HDIM];
__device__ float g_h  [BATCH*HDIM];
__device__ float g_x2 [BATCH*HDIM];
__device__ float g_ffn[BATCH*DFF];
__device__ float g_pm [BATCH*NHEADS*NSPLIT];
__device__ float g_ps [BATCH*NHEADS*NSPLIT];
__device__ float g_pa [BATCH*NHEADS*NSPLIT*HEADD];   // zero-init; empty splits stay 0

// ---------------- helpers ----------------
__device__ __forceinline__ float gelu_exact(float x) {
    return 0.5f * x * (1.0f + erff(x * 0.70710678118654752f));
}

// unbiased rounding to tf32 (A and W — biased truncation measured 2x worse err)
__device__ __forceinline__ unsigned rna_tf32(float x) {
    unsigned h;
    asm("cvt.rna.tf32.f32 %0, %1;" : "=r"(h) : "f"(x));
    return h;
}

__device__ __forceinline__ void mma_tf32(float d[4], const unsigned a[4],
                                         unsigned b0, unsigned b1) {
    asm volatile(
        "mma.sync.aligned.m16n8k8.row.col.f32.tf32.tf32.f32 "
        "{%0,%1,%2,%3}, {%4,%5,%6,%7}, {%8,%9}, {%0,%1,%2,%3};"
        : "+f"(d[0]), "+f"(d[1]), "+f"(d[2]), "+f"(d[3])
        : "r"(a[0]), "r"(a[1]), "r"(a[2]), "r"(a[3]), "r"(b0), "r"(b1));
}

__device__ __forceinline__ void cp_async16(void* smem, const void* g) {
    unsigned s = (unsigned)__cvta_generic_to_shared(smem);
    asm volatile("cp.async.cg.shared.global [%0], [%1], 16;" :: "r"(s), "l"(g));
}
__device__ __forceinline__ void cp_commit() {
    asm volatile("cp.async.commit_group;");
}
template<int N>
__device__ __forceinline__ void cp_wait() {
    asm volatile("cp.async.wait_group %0;" :: "n"(N));
}

// vector reduction: 2 contiguous fp32 adds in one RED (sm_90+)
__device__ __forceinline__ void red_add_v2(float* p, float a, float b) {
    asm volatile("red.global.add.v2.f32 [%0], {%1, %2};"
                 :: "l"(p), "f"(a), "f"(b) : "memory");
}

// ---------------- LN body (one block, one row) ----------------
__device__ __forceinline__ void ln_row(
    const float* __restrict__ xr, const float* __restrict__ g,
    const float* __restrict__ b, float* __restrict__ yr)
{
    float s = 0.f, s2 = 0.f;
    for (int i = threadIdx.x; i < HDIM; i += 256) {
        float v = xr[i]; s += v; s2 += v * v;
    }
    __shared__ float sh[16];
    int lane = threadIdx.x & 31, w = threadIdx.x >> 5;
    #pragma unroll
    for (int o = 16; o; o >>= 1) {
        s  += __shfl_xor_sync(0xffffffffu, s,  o);
        s2 += __shfl_xor_sync(0xffffffffu, s2, o);
    }
    if (lane == 0) { sh[w] = s; sh[8 + w] = s2; }
    __syncthreads();
    if (threadIdx.x == 0) {
        float S = 0.f, S2 = 0.f;
        #pragma unroll
        for (int i = 0; i < 8; i++) { S += sh[i]; S2 += sh[8 + i]; }
        sh[0] = S; sh[1] = S2;
    }
    __syncthreads();
    float mu  = sh[0] * (1.0f / HDIM);
    float var = sh[1] * (1.0f / HDIM) - mu * mu;
    float inv = rsqrtf(var + 1e-5f);
    for (int i = threadIdx.x; i < HDIM; i += 256)
        yr[i] = (xr[i] - mu) * inv * g[i] + b[i];
}

// ---------------- phase 1: ln1 rows + init q/h/ffn (independent outputs) -----
__global__ void __launch_bounds__(256) ln1_init_kernel(
    const float* __restrict__ hidden,
    const float* __restrict__ ln1g, const float* __restrict__ ln1b,
    float* __restrict__ x1,
    float* __restrict__ q, const float* __restrict__ battn,
    float* __restrict__ h, const float* __restrict__ bproj,
    float* __restrict__ ffn, const float* __restrict__ bfc)
{
    if (blockIdx.x < BATCH) {
        int row = blockIdx.x;
        ln_row(hidden + row * HDIM, ln1g, ln1b, x1 + row * HDIM);
        return;
    }
    const int gix = blockIdx.x - BATCH;
    const int gnum = gridDim.x - BATCH;
    const int n1 = BATCH * HDIM;              // q
    const int n2 = n1 + BATCH * HDIM;         // h
    const int n3 = n2 + BATCH * DFF;          // ffn
    for (int i = gix * 256 + threadIdx.x; i < n3; i += gnum * 256) {
        if (i < n1) {
            q[i] = battn[i & (HDIM - 1)];
        } else if (i < n2) {
            int j = i - n1;
            h[j] = bproj[j & (HDIM - 1)] + hidden[j];
        } else {
            int j = i - n2;
            ffn[j] = bfc[j & (DFF - 1)];
        }
    }
}

// ---------------- phase 2: ln2 rows + out = h + b_fc2 (both depend on h) ----
__global__ void __launch_bounds__(256) ln2_init_kernel(
    const float* __restrict__ h,
    const float* __restrict__ ln2g, const float* __restrict__ ln2b,
    float* __restrict__ x2,
    float* __restrict__ out, const float* __restrict__ bfc2)
{
    if (blockIdx.x < BATCH) {
        int row = blockIdx.x;
        ln_row(h + row * HDIM, ln2g, ln2b, x2 + row * HDIM);
        return;
    }
    const int gix = blockIdx.x - BATCH;
    const int gnum = gridDim.x - BATCH;
    const int n = BATCH * HDIM;
    for (int i = gix * 256 + threadIdx.x; i < n; i += gnum * 256) {
        out[i] = h[i] + bfc2[i & (HDIM - 1)];
    }
}

// ---------------- elementwise gelu (in place, float4) ----------------
__global__ void __launch_bounds__(256) gelu_kernel(float* __restrict__ x, int n4)
{
    int i = blockIdx.x * 256 + threadIdx.x;
    if (i < n4) {
        float4 v = reinterpret_cast<float4*>(x)[i];
        v.x = gelu_exact(v.x); v.y = gelu_exact(v.y);
        v.z = gelu_exact(v.z); v.w = gelu_exact(v.w);
        reinterpret_cast<float4*>(x)[i] = v;
    }
}

// ---------------- tensor-core GEMM: C[32,Nout] += A[32,K] @ W[K,:Nout] -------
// 1xTF32, A and W rna-rounded (unbiased). 3-stage cp.async ring, 3 CTAs/SM,
// one barrier per chunk. ldW = W row stride. Wave-balanced uneven split-K.
// red.v2 into bias-preinitialized C.
#define WS_FL (TKC*136)
#define AS_FL (32*36)
#define GEMM_SMEM (NSTAGE*(WS_FL+AS_FL)*4)
__global__ void __launch_bounds__(256, 3) gemm_tc(
    const float* __restrict__ A, const float* __restrict__ W,
    float* __restrict__ C, int K, int Nout, int ldW)
{
    extern __shared__ float smp[];
    float (*Ws)[TKC][136] = reinterpret_cast<float(*)[TKC][136]>(smp);
    float (*As)[32][36]   = reinterpret_cast<float(*)[32][36]>(smp + NSTAGE * WS_FL);

    int tid = threadIdx.x;
    int lane = tid & 31, warp = tid >> 5;
    int m0 = (warp & 1) * 16;
    int n0w = (warp >> 1) * 32;
    int nblk = blockIdx.x * TN;

    int cchunks = K / TKC;
    int c0 = (int)(((long long)cchunks * blockIdx.y)       / gridDim.y);
    int c1 = (int)(((long long)cchunks * (blockIdx.y + 1)) / gridDim.y);
    int kbeg = c0 * TKC;
    int nchunk = c1 - c0;

    float acc[4][4] = {};

    int am = tid >> 3, ak = (tid & 7) * 4;   // A staging coords (1 seg/thread)
    int gr = lane >> 2, kq = lane & 3;       // fragment coords

    auto prefetch = [&](int chunk) {
        int kb = kbeg + chunk * TKC;
        int s = chunk % NSTAGE;
        cp_async16(&As[s][am][ak], &A[am * K + kb + ak]);
        #pragma unroll
        for (int it = 0; it < 4; ++it) {
            int idx = it * 256 + tid;
            int kk = idx >> 5, c4 = (idx & 31) * 4;
            cp_async16(&Ws[s][kk][c4], &W[(size_t)(kb + kk) * ldW + nblk + c4]);
        }
    };

    #pragma unroll
    for (int c = 0; c < NSTAGE - 1; ++c) {
        if (c < nchunk) prefetch(c);
        cp_commit();
    }

    for (int i = 0; i < nchunk; ++i) {
        cp_wait<NSTAGE - 2>();    // group i complete
        __syncthreads();          // all warps done with compute(i-1) and see stage i
        if (i + NSTAGE - 1 < nchunk) prefetch(i + NSTAGE - 1);
        cp_commit();
        int s = i % NSTAGE;
        #pragma unroll
        for (int ks = 0; ks < 4; ++ks) {
            int k0 = ks * 8;
            unsigned ah[4];
            ah[0] = rna_tf32(As[s][m0 + gr    ][k0 + kq    ]);
            ah[1] = rna_tf32(As[s][m0 + gr + 8][k0 + kq    ]);
            ah[2] = rna_tf32(As[s][m0 + gr    ][k0 + kq + 4]);
            ah[3] = rna_tf32(As[s][m0 + gr + 8][k0 + kq + 4]);
            #pragma unroll
            for (int nt = 0; nt < 4; ++nt) {
                int nb2 = n0w + nt * 8 + gr;
                unsigned bh0 = rna_tf32(Ws[s][k0 + kq    ][nb2]);
                unsigned bh1 = rna_tf32(Ws[s][k0 + kq + 4][nb2]);
                mma_tf32(acc[nt], ah, bh0, bh1);
            }
        }
    }

    // writeout: fragment cols (cq, cq+1) are contiguous & 8B-aligned -> red.v2
    int cq = (lane & 3) * 2;
    #pragma unroll
    for (int nt = 0; nt < 4; ++nt) {
        int col = nblk + n0w + nt * 8 + cq;
        red_add_v2(&C[(m0 + gr    ) * Nout + col], acc[nt][0], acc[nt][1]);
        red_add_v2(&C[(m0 + gr + 8) * Nout + col], acc[nt][2], acc[nt][3]);
    }
}

// ---------------- attention partial: one block per (b,h,page) ----------------
__global__ void __launch_bounds__(256) attn_partial(
    const float* __restrict__ q, const float* __restrict__ kv,
    const int* __restrict__ bt, const int* __restrict__ sl,
    float* __restrict__ pm, float* __restrict__ ps, float* __restrict__ pa)
{
    int b = blockIdx.x, h = blockIdx.y, sp = blockIdx.z;
    int tid = threadIdx.x, lane = tid & 31, w = tid >> 5;
    int pidx = (b * NHEADS + h) * NSPLIT + sp;
    int seq = sl[b];
    int t0 = sp * CHUNK;
    if (t0 >= seq) {
        if (tid == 0) { pm[pidx] = -INFINITY; ps[pidx] = 0.f; }
        return;
    }
    int nt = seq - t0; if (nt > CHUNK) nt = CHUNK;

    __shared__ float qs[HEADD];
    __shared__ float sc[CHUNK];
    __shared__ int   rbs;              // page base (float index, < 2^31)
    __shared__ float sa[8][HEADD];     // per-group pass-2 partials

    if (tid < HEADD) qs[tid] = q[b * HDIM + h * HEADD + tid];
    if (tid == 0)
        rbs = bt[b * MAXBLK + sp] * (PAGE * NHEADS * HEADD) + h * HEADD;
    __syncthreads();
    int rb = rbs;

    const float scale = 0.08838834764831845f;  // 1/sqrt(128)
    float4 qx = reinterpret_cast<const float4*>(qs)[lane];

    // pass 1: scores. 4 tokens/warp/iter (loads clamped to page row 63 — always
    // resident; stores guarded by nt). Interleaved shfl chains pipeline.
    for (int tb = w * 4; tb < nt; tb += 32) {
        int u1 = min(tb + 1, 63), u2 = min(tb + 2, 63), u3 = min(tb + 3, 63);
        const float* base = kv + rb;
        float4 ka = reinterpret_cast<const float4*>(base + tb * (NHEADS * HEADD))[lane];
        float4 kb2 = reinterpret_cast<const float4*>(base + u1 * (NHEADS * HEADD))[lane];
        float4 kc2 = reinterpret_cast<const float4*>(base + u2 * (NHEADS * HEADD))[lane];
        float4 kd2 = reinterpret_cast<const float4*>(base + u3 * (NHEADS * HEADD))[lane];
        float d0 = ka.x  * qx.x + ka.y  * qx.y + ka.z  * qx.z + ka.w  * qx.w;
        float d1 = kb2.x * qx.x + kb2.y * qx.y + kb2.z * qx.z + kb2.w * qx.w;
        float d2 = kc2.x * qx.x + kc2.y * qx.y + kc2.z * qx.z + kc2.w * qx.w;
        float d3 = kd2.x * qx.x + kd2.y * qx.y + kd2.z * qx.z + kd2.w * qx.w;
        #pragma unroll
        for (int o = 16; o; o >>= 1) {
            d0 += __shfl_xor_sync(0xffffffffu, d0, o);
            d1 += __shfl_xor_sync(0xffffffffu, d1, o);
            d2 += __shfl_xor_sync(0xffffffffu, d2, o);
            d3 += __shfl_xor_sync(0xffffffffu, d3, o);
        }
        if (lane == 0) {
            sc[tb] = d0 * scale;
            if (tb + 1 < nt) sc[tb + 1] = d1 * scale;
            if (tb + 2 < nt) sc[tb + 2] = d2 * scale;
            if (tb + 3 < nt) sc[tb + 3] = d3 * scale;
        }
    }
    __syncthreads();

    // softmax stats in ONE warp (nt <= 64 -> 2 values/lane), then one barrier.
    if (w == 0) {
        float v0 = (lane      < nt) ? sc[lane]      : -INFINITY;
        float v1 = (lane + 32 < nt) ? sc[lane + 32] : -INFINITY;
        float m = fmaxf(v0, v1);
        #pragma unroll
        for (int o = 16; o; o >>= 1) m = fmaxf(m, __shfl_xor_sync(0xffffffffu, m, o));
        float e0 = (lane      < nt) ? __expf(v0 - m) : 0.f;
        float e1 = (lane + 32 < nt) ? __expf(v1 - m) : 0.f;
        if (lane      < nt) sc[lane]      = e0;
        if (lane + 32 < nt) sc[lane + 32] = e1;
        float s = e0 + e1;
        #pragma unroll
        for (int o = 16; o; o >>= 1) s += __shfl_xor_sync(0xffffffffu, s, o);
        if (lane == 0) { pm[pidx] = m; ps[pidx] = s; }
    }
    __syncthreads();

    // pass 2 (float4): each warp streams whole 512B V rows. 8 token-groups;
    // group g handles tokens t = g, g+8, g+16, ... ; lane covers 4 dims.
    {
        int d4 = lane * 4;
        int grp = w;                     // 0..7
        const float* Vb4 = kv + (size_t)NUMBLK * PAGE * NHEADS * HEADD + rb + d4;
        float4 a0 = {0.f, 0.f, 0.f, 0.f}, a1 = {0.f, 0.f, 0.f, 0.f};
        int t = grp;
        for (; t + 8 < nt; t += 16) {
            float4 v0 = *reinterpret_cast<const float4*>(Vb4 + t       * (NHEADS * HEADD));
            float4 v1 = *reinterpret_cast<const float4*>(Vb4 + (t + 8) * (NHEADS * HEADD));
            float s0 = sc[t], s1 = sc[t + 8];
            a0.x += s0 * v0.x; a0.y += s0 * v0.y; a0.z += s0 * v0.z; a0.w += s0 * v0.w;
            a1.x += s1 * v1.x; a1.y += s1 * v1.y; a1.z += s1 * v1.z; a1.w += s1 * v1.w;
        }
        if (t < nt) {
            float4 v0 = *reinterpret_cast<const float4*>(Vb4 + t * (NHEADS * HEADD));
            float s0 = sc[t];
            a0.x += s0 * v0.x; a0.y += s0 * v0.y; a0.z += s0 * v0.z; a0.w += s0 * v0.w;
        }
        sa[grp][d4    ] = a0.x + a1.x;
        sa[grp][d4 + 1] = a0.y + a1.y;
        sa[grp][d4 + 2] = a0.z + a1.z;
        sa[grp][d4 + 3] = a0.w + a1.w;
    }
    __syncthreads();
    if (tid < HEADD) {
        float r = 0.f;
        #pragma unroll
        for (int gI = 0; gI < 8; gI++) r += sa[gI][tid];
        pa[(size_t)pidx * HEADD + tid] = r;
    }
}

// ---------------- attention combine: grid (B, H, 2), 256 threads ------------
// z selects 64 dims; 4 split-groups of 8 -> 8 independent loads per thread.
// Warp 0 computes the 32 softmax weights once per block.
__global__ void __launch_bounds__(256) attn_combine(
    const float* __restrict__ pm, const float* __restrict__ ps,
    const float* __restrict__ pa, float* __restrict__ out)
{
    int b = blockIdx.x, h = blockIdx.y, z = blockIdx.z;
    int idx = b * NHEADS + h;
    int tid = threadIdx.x;
    int d = z * 64 + (tid & 63), g = tid >> 6;   // g in 0..3: splits g*8..g*8+7
    __shared__ float wgt[NSPLIT];
    __shared__ float dens;
    __shared__ float part[4][64];

    if (tid < 32) {
        float mi = pm[idx * NSPLIT + tid];
        float si = ps[idx * NSPLIT + tid];
        float mv = (si > 0.f) ? mi : -INFINITY;
        float M = mv;
        #pragma unroll
        for (int o = 16; o; o >>= 1) M = fmaxf(M, __shfl_xor_sync(0xffffffffu, M, o));
        float e = (si > 0.f) ? __expf(mi - M) : 0.f;
        float den = e * si;
        #pragma unroll
        for (int o = 16; o; o >>= 1) den += __shfl_xor_sync(0xffffffffu, den, o);
        wgt[tid] = e;
        if (tid == 0) dens = den;
    }
    __syncthreads();

    const float* pab = pa + ((size_t)idx * NSPLIT + g * 8) * HEADD + d;
    float a0 = 0.f, a1 = 0.f, a2 = 0.f, a3 = 0.f;
    #pragma unroll
    for (int k = 0; k < 8; k += 4) {
        int i = g * 8 + k;
        a0 += wgt[i    ] * pab[(k    ) * HEADD];
        a1 += wgt[i + 1] * pab[(k + 1) * HEADD];
        a2 += wgt[i + 2] * pab[(k + 2) * HEADD];
        a3 += wgt[i + 3] * pab[(k + 3) * HEADD];
    }
    part[g][tid & 63] = (a0 + a1) + (a2 + a3);
    __syncthreads();
    if (g == 0)
        out[b * HDIM + h * HEADD + d] =
            (part[0][tid & 63] + part[1][tid & 63] +
             part[2][tid & 63] + part[3][tid & 63]) / dens;
}

// ---------------- host launcher ----------------
extern "C" void kernel_launch(void* const* d_in, const int* in_sizes, int n_in,
                              void* d_out, int out_size)
{
    const float* hidden = (const float*)d_in[0];
    const float* kv     = (const float*)d_in[1];
    const int*   bt     = (const int*)d_in[2];
    const int*   sl     = (const int*)d_in[3];
    int p = (n_in > 4 && in_sizes[4] == 1) ? 5 : 4;  // skip max_seq_len if present
    const float* ln1g  = (const float*)d_in[p + 0];
    const float* ln1b  = (const float*)d_in[p + 1];
    const float* ln2g  = (const float*)d_in[p + 2];
    const float* ln2b  = (const float*)d_in[p + 3];
    const float* wattn = (const float*)d_in[p + 4];
    const float* battn = (const float*)d_in[p + 5];
    const float* wproj = (const float*)d_in[p + 6];
    const float* bproj = (const float*)d_in[p + 7];
    const float* wfc   = (const float*)d_in[p + 8];
    const float* bfc   = (const float*)d_in[p + 9];
    const float* wfc2  = (const float*)d_in[p + 10];
    const float* bfc2  = (const float*)d_in[p + 11];
    float* out = (float*)d_out;

    float *x1, *qbuf, *att, *h, *x2, *ffn, *pm, *ps, *pa;
    cudaGetSymbolAddress((void**)&x1,   g_x1);
    cudaGetSymbolAddress((void**)&qbuf, g_q);
    cudaGetSymbolAddress((void**)&att,  g_att);
    cudaGetSymbolAddress((void**)&h,    g_h);
    cudaGetSymbolAddress((void**)&x2,   g_x2);
    cudaGetSymbolAddress((void**)&ffn,  g_ffn);
    cudaGetSymbolAddress((void**)&pm,   g_pm);
    cudaGetSymbolAddress((void**)&ps,   g_ps);
    cudaGetSymbolAddress((void**)&pa,   g_pa);

    cudaFuncSetAttribute(gemm_tc,
        cudaFuncAttributeMaxDynamicSharedMemorySize, GEMM_SMEM);

    // 1. ln1 rows (blocks 0-31) + q/h/ffn bias-inits (rest), one launch
    ln1_init_kernel<<<BATCH + 416, 256>>>(hidden, ln1g, ln1b, x1,
                                          qbuf, battn, h, bproj, ffn, bfc);
    // 2. q = x1 @ w_attn[:, :H] + b_attn[:H]   (16 x 27 = 432 CTAs -> 3/SM)
    gemm_tc<<<dim3(HDIM / TN, 27), 256, GEMM_SMEM>>>(x1, wattn, qbuf, HDIM, HDIM, QKV_N);
    // 3. attention (flash-decode, 32-way page split)
    attn_partial<<<dim3(BATCH, NHEADS, NSPLIT), 256>>>(qbuf, kv, bt, sl, pm, ps, pa);
    attn_combine<<<dim3(BATCH, NHEADS, 2), 256>>>(pm, ps, pa, att);
    // 4. h += attn @ w_proj   (16 x 27 = 432 CTAs)
    gemm_tc<<<dim3(HDIM / TN, 27), 256, GEMM_SMEM>>>(att, wproj, h, HDIM, HDIM, HDIM);
    // 5. ln2 rows + out = h + b_fc2, one launch
    ln2_init_kernel<<<BATCH + 128, 256>>>(h, ln2g, ln2b, x2, out, bfc2);
    // 6. ffn += x2 @ w_fc   (64 x 7 = 448 CTAs)
    gemm_tc<<<dim3(DFF / TN, 7), 256, GEMM_SMEM>>>(x2, wfc, ffn, HDIM, DFF, DFF);
    // 6b. gelu(ffn) in place
    gelu_kernel<<<(BATCH * DFF / 4 + 255) / 256, 256>>>(ffn, BATCH * DFF / 4);
    // 7. out += gelu(ffn) @ w_fc2   (16 x 27 = 432 CTAs)
    gemm_tc<<<dim3(HDIM / TN, 27), 256, GEMM_SMEM>>>(ffn, wfc2, out, DFF, HDIM, HDIM);
}